// round 3
// baseline (speedup 1.0000x reference)
#include <cuda_runtime.h>

// SubjectLayer: per-sample subject-specific 1x1 conv.
//   x:     [B=256, C=256, 1, W=3000] f32
//   weight:[S=128, C_out=256, C_in=256] f32
//   bias:  [S=128, C_out=256] f32
//   subj:  [B=256] int32  (JAX x64 disabled -> "int64" request degrades to int32)
//   out:   [B, C_out, 1, W] f32
// Per sample b: out = weight[subj[b]] @ x[b] + bias[subj[b]]
//   M = 256 (C_out), K = 256 (C_in), N = 3000 (W)

#define TM 128
#define TN 128
#define TK 16

__global__ __launch_bounds__(256, 2)
void subject_sgemm_kernel(const float* __restrict__ x,
                          const float* __restrict__ weight,
                          const float* __restrict__ bias,
                          const int* __restrict__ subj,
                          float* __restrict__ out)
{
    const int C = 256;
    const int N = 3000;

    const int b  = blockIdx.z;
    const int m0 = blockIdx.y * TM;   // output-channel tile base
    const int n0 = blockIdx.x * TN;   // spatial tile base

    const int s = subj[b];
    const float* __restrict__ Wm = weight + (size_t)s * C * C;   // [M, K] row-major
    const float* __restrict__ X  = x      + (size_t)b * C * N;   // [K, N]
    const float* __restrict__ Bv = bias   + (size_t)s * C;
    float* __restrict__ O        = out    + (size_t)b * C * N;   // [M, N]

    __shared__ float As[TK][TM];       // A tile, K-major (transposed W tile)
    __shared__ float Bs[TK][TN];       // X tile

    const int tid = threadIdx.x;
    const int ty  = tid >> 4;          // 0..15
    const int tx  = tid & 15;          // 0..15
    const int row0 = ty * 8;           // local m base for this thread
    const int col0 = tx * 8;           // local n base for this thread

    float acc[8][8];
    #pragma unroll
    for (int i = 0; i < 8; i++)
        #pragma unroll
        for (int j = 0; j < 8; j++)
            acc[i][j] = 0.0f;

    for (int k0 = 0; k0 < C; k0 += TK) {
        // ---- Load W tile [128 rows m, 16 cols k] -> As[k][m] (transposed) ----
        // 2048 floats = 512 float4; 2 per thread. float4 along K (W is K-contiguous).
        #pragma unroll
        for (int i = 0; i < 2; i++) {
            int idx = tid + i * 256;        // 0..511
            int m   = idx >> 2;             // 0..127
            int k4  = (idx & 3) * 4;        // 0,4,8,12
            float4 v = *reinterpret_cast<const float4*>(
                &Wm[(size_t)(m0 + m) * C + k0 + k4]);
            As[k4 + 0][m] = v.x;
            As[k4 + 1][m] = v.y;
            As[k4 + 2][m] = v.z;
            As[k4 + 3][m] = v.w;
        }
        // ---- Load X tile [16 rows k, 128 cols n] -> Bs[k][n] ----
        // float4 along n (coalesced). Tail tile: n0=2944, valid cols 0..55
        // (3000-2944=56, multiple of 4, so every float4 is all-valid or all-invalid).
        #pragma unroll
        for (int i = 0; i < 2; i++) {
            int idx = tid + i * 256;        // 0..511
            int k   = idx >> 5;             // 0..15
            int n4  = (idx & 31) * 4;       // 0..124
            int n   = n0 + n4;
            float4 v;
            if (n < N) {
                v = *reinterpret_cast<const float4*>(&X[(size_t)(k0 + k) * N + n]);
            } else {
                v = make_float4(0.f, 0.f, 0.f, 0.f);
            }
            *reinterpret_cast<float4*>(&Bs[k][n4]) = v;
        }
        __syncthreads();

        // ---- Compute 16 k-steps, 8x8 outer product per thread ----
        #pragma unroll
        for (int k = 0; k < TK; k++) {
            float a[8], bb[8];
            float4 a0 = *reinterpret_cast<const float4*>(&As[k][row0]);
            float4 a1 = *reinterpret_cast<const float4*>(&As[k][row0 + 4]);
            float4 b0 = *reinterpret_cast<const float4*>(&Bs[k][col0]);
            float4 b1 = *reinterpret_cast<const float4*>(&Bs[k][col0 + 4]);
            a[0]=a0.x; a[1]=a0.y; a[2]=a0.z; a[3]=a0.w;
            a[4]=a1.x; a[5]=a1.y; a[6]=a1.z; a[7]=a1.w;
            bb[0]=b0.x; bb[1]=b0.y; bb[2]=b0.z; bb[3]=b0.w;
            bb[4]=b1.x; bb[5]=b1.y; bb[6]=b1.z; bb[7]=b1.w;
            #pragma unroll
            for (int i = 0; i < 8; i++)
                #pragma unroll
                for (int j = 0; j < 8; j++)
                    acc[i][j] = fmaf(a[i], bb[j], acc[i][j]);
        }
        __syncthreads();
    }

    // ---- Epilogue: add bias, store ----
    #pragma unroll
    for (int i = 0; i < 8; i++) {
        int m = m0 + row0 + i;
        float bv = Bv[m];
        #pragma unroll
        for (int j = 0; j < 8; j += 4) {
            int n = n0 + col0 + j;
            if (n < N) {
                float4 v;
                v.x = acc[i][j + 0] + bv;
                v.y = acc[i][j + 1] + bv;
                v.z = acc[i][j + 2] + bv;
                v.w = acc[i][j + 3] + bv;
                *reinterpret_cast<float4*>(&O[(size_t)m * N + n]) = v;
            }
        }
    }
}

extern "C" void kernel_launch(void* const* d_in, const int* in_sizes, int n_in,
                              void* d_out, int out_size) {
    const float* x      = (const float*)d_in[0];   // [256,256,1,3000]
    const float* weight = (const float*)d_in[1];   // [128,256,256]
    const float* bias   = (const float*)d_in[2];   // [128,256]
    const int*   subj   = (const int*)d_in[3];     // [256] int32
    float*       out    = (float*)d_out;           // [256,256,1,3000]

    const int B = 256;
    const int N = 3000;

    dim3 block(256);
    dim3 grid((N + TN - 1) / TN, 256 / TM, B);  // (24, 2, 256)
    subject_sgemm_kernel<<<grid, block>>>(x, weight, bias, subj, out);
}

// round 4
// speedup vs baseline: 3.3199x; 3.3199x over previous
#include <cuda_runtime.h>
#include <cstdint>

// SubjectLayer: per-sample subject 1x1 conv == 256 SGEMMs (M=256,K=256,N=3000)
// tf32 mma.sync.m16n8k8 tensor-core implementation.
//   x:[256,256,1,3000] f32, weight:[128,256,256] f32, bias:[128,256] f32,
//   subj:[256] int32, out:[256,256,1,3000] f32

#define TM 128
#define TN 128
#define TK 32
#define NCHUNK 8                 // K=256 / 32
#define AS_STRIDE 36             // 32 + pad 4 -> conflict-free frag LDS
#define BS_STRIDE 136            // 128 + pad 8
#define AS_TILE (128 * AS_STRIDE)   // floats per A buffer
#define BS_TILE (32 * BS_STRIDE)    // floats per B buffer
#define SMEM_FLOATS (2 * AS_TILE + 2 * BS_TILE)
#define SMEM_BYTES (SMEM_FLOATS * 4)   // 71680

__device__ __forceinline__ uint32_t f2tf32(float f) {
    uint32_t r;
    asm("cvt.rna.tf32.f32 %0, %1;" : "=r"(r) : "f"(f));
    return r;
}

__device__ __forceinline__ void cp16(uint32_t dst, const void* src) {
    asm volatile("cp.async.cg.shared.global [%0], [%1], 16;\n" :: "r"(dst), "l"(src));
}
__device__ __forceinline__ void cp16z(uint32_t dst, const void* src, int src_size) {
    asm volatile("cp.async.cg.shared.global [%0], [%1], 16, %2;\n"
                 :: "r"(dst), "l"(src), "r"(src_size));
}

__device__ __forceinline__ void mma_tf32(float* d, const uint32_t* a,
                                         uint32_t b0, uint32_t b1) {
    asm volatile(
        "mma.sync.aligned.m16n8k8.row.col.f32.tf32.tf32.f32 "
        "{%0,%1,%2,%3}, {%4,%5,%6,%7}, {%8,%9}, {%0,%1,%2,%3};\n"
        : "+f"(d[0]), "+f"(d[1]), "+f"(d[2]), "+f"(d[3])
        : "r"(a[0]), "r"(a[1]), "r"(a[2]), "r"(a[3]), "r"(b0), "r"(b1));
}

extern __shared__ float smem[];

__global__ void subject_tf32_kernel(const float* __restrict__ x,
                                    const float* __restrict__ weight,
                                    const float* __restrict__ bias,
                                    const int* __restrict__ subj,
                                    float* __restrict__ out)
{
    const int C = 256;
    const int N = 3000;

    const int b  = blockIdx.z;
    const int m0 = blockIdx.y * TM;
    const int n0 = blockIdx.x * TN;

    const int s = subj[b];
    const float* __restrict__ Wm = weight + (size_t)s * C * C;   // [M,K] row-major
    const float* __restrict__ X  = x      + (size_t)b * C * N;   // [K,N]
    const float* __restrict__ Bv = bias   + (size_t)s * C;
    float* __restrict__ O        = out    + (size_t)b * C * N;   // [M,N]

    float* As = smem;                 // [2][128][AS_STRIDE]
    float* Bs = smem + 2 * AS_TILE;   // [2][32][BS_STRIDE]
    const uint32_t as_u32 = (uint32_t)__cvta_generic_to_shared(As);
    const uint32_t bs_u32 = (uint32_t)__cvta_generic_to_shared(Bs);

    const int tid   = threadIdx.x;
    const int wid   = tid >> 5;
    const int lane  = tid & 31;
    const int warp_m = wid & 3;       // 0..3 -> 32-row slabs
    const int warp_n = wid >> 2;      // 0..1 -> 64-col slabs
    const int group = lane >> 2;      // 0..7
    const int tig   = lane & 3;       // 0..3

    const int am = warp_m * 32;       // warp m base within tile
    const int bn = warp_n * 64;       // warp n base within tile

    float acc[2][8][4];
    #pragma unroll
    for (int mi = 0; mi < 2; mi++)
        #pragma unroll
        for (int ni = 0; ni < 8; ni++)
            #pragma unroll
            for (int r = 0; r < 4; r++)
                acc[mi][ni][r] = 0.0f;

    // Precomputed per-thread load coordinates (4 float4 each for A and B).
    const int a_m  = tid >> 3;            // base idx: m = idx/8
    const int a_k4 = (tid & 7) << 2;      // (idx%8)*4
    const int b_k  = tid >> 5;            // idx/32
    const int b_n4 = (tid & 31) << 2;     // (idx%32)*4

    auto load_chunk = [&](int buf, int k0) {
        uint32_t abase = as_u32 + (uint32_t)buf * AS_TILE * 4;
        uint32_t bbase = bs_u32 + (uint32_t)buf * BS_TILE * 4;
        #pragma unroll
        for (int j = 0; j < 4; j++) {
            int m = a_m + j * 32;                       // idx/8, idx = tid + j*256
            cp16(abase + (uint32_t)(m * AS_STRIDE + a_k4) * 4,
                 Wm + (size_t)(m0 + m) * C + k0 + a_k4);
        }
        #pragma unroll
        for (int j = 0; j < 4; j++) {
            int k = b_k + j * 8;                        // idx/32
            int n = n0 + b_n4;
            int ok = (n < N);
            cp16z(bbase + (uint32_t)(k * BS_STRIDE + b_n4) * 4,
                  X + (size_t)(k0 + k) * N + (ok ? n : 0),
                  ok ? 16 : 0);
        }
        asm volatile("cp.async.commit_group;\n");
    };

    auto compute_chunk = [&](int buf) {
        const float* A = As + buf * AS_TILE;
        const float* B = Bs + buf * BS_TILE;
        #pragma unroll
        for (int kk = 0; kk < 4; kk++) {
            const int k8 = kk * 8;
            uint32_t af[2][4];
            #pragma unroll
            for (int mi = 0; mi < 2; mi++) {
                const int r = am + mi * 16;
                af[mi][0] = f2tf32(A[(r + group)     * AS_STRIDE + k8 + tig]);
                af[mi][1] = f2tf32(A[(r + group + 8) * AS_STRIDE + k8 + tig]);
                af[mi][2] = f2tf32(A[(r + group)     * AS_STRIDE + k8 + tig + 4]);
                af[mi][3] = f2tf32(A[(r + group + 8) * AS_STRIDE + k8 + tig + 4]);
            }
            #pragma unroll
            for (int ni = 0; ni < 8; ni++) {
                uint32_t b0 = f2tf32(B[(k8 + tig)     * BS_STRIDE + bn + ni * 8 + group]);
                uint32_t b1 = f2tf32(B[(k8 + tig + 4) * BS_STRIDE + bn + ni * 8 + group]);
                mma_tf32(acc[0][ni], af[0], b0, b1);
                mma_tf32(acc[1][ni], af[1], b0, b1);
            }
        }
    };

    // Software pipeline: double-buffered cp.async.
    load_chunk(0, 0);

    #pragma unroll 1
    for (int c = 0; c < NCHUNK; c++) {
        if (c + 1 < NCHUNK) {
            load_chunk((c + 1) & 1, (c + 1) * TK);
            asm volatile("cp.async.wait_group 1;\n");
        } else {
            asm volatile("cp.async.wait_group 0;\n");
        }
        __syncthreads();
        compute_chunk(c & 1);
        __syncthreads();
    }

    // Epilogue: bias add + store (float2 per accumulator pair).
    #pragma unroll
    for (int mi = 0; mi < 2; mi++) {
        const int mrow = m0 + am + mi * 16 + group;
        const float bv0 = Bv[mrow];
        const float bv1 = Bv[mrow + 8];
        #pragma unroll
        for (int ni = 0; ni < 8; ni++) {
            const int n = n0 + bn + ni * 8 + tig * 2;
            if (n < N) {
                float2 v0 = make_float2(acc[mi][ni][0] + bv0, acc[mi][ni][1] + bv0);
                *reinterpret_cast<float2*>(&O[(size_t)mrow * N + n]) = v0;
                float2 v1 = make_float2(acc[mi][ni][2] + bv1, acc[mi][ni][3] + bv1);
                *reinterpret_cast<float2*>(&O[(size_t)(mrow + 8) * N + n]) = v1;
            }
        }
    }
}

extern "C" void kernel_launch(void* const* d_in, const int* in_sizes, int n_in,
                              void* d_out, int out_size) {
    const float* x      = (const float*)d_in[0];
    const float* weight = (const float*)d_in[1];
    const float* bias   = (const float*)d_in[2];
    const int*   subj   = (const int*)d_in[3];
    float*       out    = (float*)d_out;

    const int B = 256;
    const int N = 3000;

    cudaFuncSetAttribute(subject_tf32_kernel,
                         cudaFuncAttributeMaxDynamicSharedMemorySize, SMEM_BYTES);

    dim3 block(256);
    dim3 grid((N + TN - 1) / TN, 256 / TM, B);   // (24, 2, 256)
    subject_tf32_kernel<<<grid, block, SMEM_BYTES>>>(x, weight, bias, subj, out);
}